// round 1
// baseline (speedup 1.0000x reference)
#include <cuda_runtime.h>
#include <stdint.h>

#define HD      256
#define N_DRUG  50000
#define N_TGT   20000

// Precomputed per-entity hidden pre-activations (u = z @ W1_part), fp32.
__device__ float g_ud[(size_t)N_DRUG * HD];   // 51.2 MB
__device__ float g_ut[(size_t)N_TGT  * HD];   // 20.5 MB
__device__ int   g_idx64;                     // 1 if row/col are int64, 0 if int32

// ---------------------------------------------------------------------------
// Detect whether the index arrays are int64 or int32 (JAX x64 flag ambiguity).
// If data is int32, the int64 reinterpretation of element j is
// v[2j] + (v[2j+1] << 32); since values are uniform in [0, 50000), the chance
// that 64 consecutive "high words" are all zero is ~(1/50000)^64 ~ 0.
// ---------------------------------------------------------------------------
__global__ void detect_idx_kernel(const unsigned long long* __restrict__ row) {
    if (threadIdx.x == 0 && blockIdx.x == 0) {
        int ok = 1;
        #pragma unroll 1
        for (int i = 0; i < 64; ++i) {
            if (row[i] >= (unsigned long long)N_DRUG) { ok = 0; break; }
        }
        g_idx64 = ok;
    }
}

// ---------------------------------------------------------------------------
// SGEMM: C[M,256] = A[M,256] @ B[256,256]   (all row-major, fp32)
// 128x128 block tile, BK=8, 256 threads, 8x8 per-thread register tile.
// ---------------------------------------------------------------------------
__global__ __launch_bounds__(256, 2)
void sgemm_kernel(const float* __restrict__ A, const float* __restrict__ B,
                  float* __restrict__ C, int M) {
    const int N = HD, K = HD;

    __shared__ float As[8][128];   // transposed A tile: As[k][m]
    __shared__ float Bs[8][128];   // Bs[k][n]

    const int tid = threadIdx.x;
    const int bm  = blockIdx.y * 128;
    const int bn  = blockIdx.x * 128;

    // A tile load mapping: 128 rows x 8 cols = 256 float4
    const int rowA = tid >> 1;
    const int colA = (tid & 1) * 4;
    // B tile load mapping: 8 rows x 128 cols = 256 float4
    const int rowB = tid >> 5;
    const int colB = (tid & 31) * 4;

    // 16x16 thread grid, each thread owns an 8x8 output tile
    const int tr = (tid >> 4) << 3;   // 0..120
    const int tc = (tid & 15) << 3;   // 0..120

    float acc[8][8];
    #pragma unroll
    for (int i = 0; i < 8; ++i)
        #pragma unroll
        for (int j = 0; j < 8; ++j) acc[i][j] = 0.f;

    const int gRowA = bm + rowA;
    const bool aValid = (gRowA < M);

    for (int k0 = 0; k0 < K; k0 += 8) {
        float4 a4 = make_float4(0.f, 0.f, 0.f, 0.f);
        if (aValid)
            a4 = *reinterpret_cast<const float4*>(A + (size_t)gRowA * K + k0 + colA);
        As[colA + 0][rowA] = a4.x;
        As[colA + 1][rowA] = a4.y;
        As[colA + 2][rowA] = a4.z;
        As[colA + 3][rowA] = a4.w;

        float4 b4 = *reinterpret_cast<const float4*>(B + (size_t)(k0 + rowB) * N + bn + colB);
        *reinterpret_cast<float4*>(&Bs[rowB][colB]) = b4;

        __syncthreads();

        #pragma unroll
        for (int kk = 0; kk < 8; ++kk) {
            float4 a0 = *reinterpret_cast<const float4*>(&As[kk][tr]);
            float4 a1 = *reinterpret_cast<const float4*>(&As[kk][tr + 4]);
            float4 b0 = *reinterpret_cast<const float4*>(&Bs[kk][tc]);
            float4 b1 = *reinterpret_cast<const float4*>(&Bs[kk][tc + 4]);
            float ar[8] = {a0.x, a0.y, a0.z, a0.w, a1.x, a1.y, a1.z, a1.w};
            float br[8] = {b0.x, b0.y, b0.z, b0.w, b1.x, b1.y, b1.z, b1.w};
            #pragma unroll
            for (int i = 0; i < 8; ++i)
                #pragma unroll
                for (int j = 0; j < 8; ++j)
                    acc[i][j] = fmaf(ar[i], br[j], acc[i][j]);
        }
        __syncthreads();
    }

    #pragma unroll
    for (int i = 0; i < 8; ++i) {
        int r = bm + tr + i;
        if (r < M) {
            float* cp = C + (size_t)r * N + bn + tc;
            *reinterpret_cast<float4*>(cp)     = make_float4(acc[i][0], acc[i][1], acc[i][2], acc[i][3]);
            *reinterpret_cast<float4*>(cp + 4) = make_float4(acc[i][4], acc[i][5], acc[i][6], acc[i][7]);
    }
    }
}

// ---------------------------------------------------------------------------
// Edge kernel: out[e] = relu(u_d[row[e]] + u_t[col[e]] + b1) . W2 + b2
// One warp per edge; lane l handles float4 chunks l and l+32 (coalesced 128B).
// ---------------------------------------------------------------------------
__global__ __launch_bounds__(256)
void edge_kernel(const void* __restrict__ rowp, const void* __restrict__ colp,
                 const float* __restrict__ b1, const float* __restrict__ W2,
                 const float* __restrict__ b2, float* __restrict__ out, int E) {
    __shared__ float s_b1[HD];
    __shared__ float s_w2[HD];
    const int tid = threadIdx.x;
    s_b1[tid] = b1[tid];
    s_w2[tid] = W2[tid];
    __syncthreads();

    const int warp = tid >> 5;
    const int lane = tid & 31;
    const int e = blockIdx.x * 8 + warp;
    if (e >= E) return;

    long long r, c;
    if (g_idx64) {
        r = reinterpret_cast<const long long*>(rowp)[e];
        c = reinterpret_cast<const long long*>(colp)[e];
    } else {
        r = reinterpret_cast<const int*>(rowp)[e];
        c = reinterpret_cast<const int*>(colp)[e];
    }

    const float4* ud = reinterpret_cast<const float4*>(g_ud + (size_t)r * HD);
    const float4* ut = reinterpret_cast<const float4*>(g_ut + (size_t)c * HD);
    const float4* sb = reinterpret_cast<const float4*>(s_b1);
    const float4* sw = reinterpret_cast<const float4*>(s_w2);

    float sum = 0.f;
    #pragma unroll
    for (int it = 0; it < 2; ++it) {
        int idx = lane + it * 32;       // float4 index within the 256-dim row
        float4 a = ud[idx];
        float4 b = ut[idx];
        float4 bb = sb[idx];
        float4 ww = sw[idx];
        float h0 = fmaxf(a.x + b.x + bb.x, 0.f);
        float h1 = fmaxf(a.y + b.y + bb.y, 0.f);
        float h2 = fmaxf(a.z + b.z + bb.z, 0.f);
        float h3 = fmaxf(a.w + b.w + bb.w, 0.f);
        sum = fmaf(h0, ww.x, sum);
        sum = fmaf(h1, ww.y, sum);
        sum = fmaf(h2, ww.z, sum);
        sum = fmaf(h3, ww.w, sum);
    }

    #pragma unroll
    for (int off = 16; off > 0; off >>= 1)
        sum += __shfl_down_sync(0xffffffffu, sum, off);

    if (lane == 0) out[e] = sum + b2[0];
}

// ---------------------------------------------------------------------------
// Launch
// inputs: 0=z_drug[50000,256] 1=z_target[20000,256] 2=row[E] 3=col[E]
//         4=W1[512,256] 5=b1[256] 6=W2[256,1] 7=b2[1]
// ---------------------------------------------------------------------------
extern "C" void kernel_launch(void* const* d_in, const int* in_sizes, int n_in,
                              void* d_out, int out_size) {
    const float* z_drug   = (const float*)d_in[0];
    const float* z_target = (const float*)d_in[1];
    const void*  rowp     = d_in[2];
    const void*  colp     = d_in[3];
    const float* W1       = (const float*)d_in[4];
    const float* b1       = (const float*)d_in[5];
    const float* W2       = (const float*)d_in[6];
    const float* b2       = (const float*)d_in[7];
    float* out = (float*)d_out;

    const int E = out_size;  // 500000

    float* ud;
    float* ut;
    cudaGetSymbolAddress((void**)&ud, g_ud);
    cudaGetSymbolAddress((void**)&ut, g_ut);

    // index-width detection (graph-capturable, deterministic)
    detect_idx_kernel<<<1, 32>>>((const unsigned long long*)rowp);

    // u_drug = z_drug @ W1[0:256,:]
    {
        dim3 grid(HD / 128, (N_DRUG + 127) / 128);
        sgemm_kernel<<<grid, 256>>>(z_drug, W1, ud, N_DRUG);
    }
    // u_target = z_target @ W1[256:512,:]
    {
        dim3 grid(HD / 128, (N_TGT + 127) / 128);
        sgemm_kernel<<<grid, 256>>>(z_target, W1 + (size_t)HD * HD, ut, N_TGT);
    }

    // edge phase: 8 edges per 256-thread block
    {
        int blocks = (E + 7) / 8;
        edge_kernel<<<blocks, 256>>>(rowp, colp, b1, W2, b2, out, E);
    }
}

// round 3
// speedup vs baseline: 1.8374x; 1.8374x over previous
#include <cuda_runtime.h>
#include <cuda_fp16.h>
#include <stdint.h>

#define HD      256
#define N_DRUG  50000
#define N_TGT   20000
#define NBLK_D  391   // ceil(50000/128)
#define NBLK_T  157   // ceil(20000/128)

// ---------------- device scratch (no allocation allowed) -------------------
__device__ __align__(16) __half g_ud[(size_t)N_DRUG * HD];   // 25.6 MB fp16
__device__ __align__(16) __half g_ut[(size_t)N_TGT  * HD];   // 10.2 MB fp16
// W1 transposed to [n][k] fp16 (K-contiguous rows => "col-major B" for mma.sync)
__device__ __align__(16) __half g_wd[HD * HD];
__device__ __align__(16) __half g_wt[HD * HD];
__device__ int g_idx64;

__device__ __forceinline__ uint32_t smem_u32(const void* p) {
    uint32_t a;
    asm("{ .reg .u64 t; cvta.to.shared.u64 t, %1; cvt.u32.u64 %0, t; }" : "=r"(a) : "l"(p));
    return a;
}

// ---------------------------------------------------------------------------
// index width detection (int64 vs int32 ambiguity of the reference dtypes)
// ---------------------------------------------------------------------------
__global__ void detect_idx_kernel(const unsigned long long* __restrict__ row) {
    if (threadIdx.x == 0 && blockIdx.x == 0) {
        int ok = 1;
        #pragma unroll 1
        for (int i = 0; i < 64; ++i)
            if (row[i] >= (unsigned long long)N_DRUG) { ok = 0; break; }
        g_idx64 = ok;
    }
}

// ---------------------------------------------------------------------------
// W1 prep: transpose [k][n] -> [n][k], fp32 -> fp16
// ---------------------------------------------------------------------------
__global__ void prep_w1_kernel(const float* __restrict__ W1) {
    int idx = blockIdx.x * 256 + threadIdx.x;   // 0 .. 512*256-1
    int k = idx >> 8;
    int n = idx & 255;
    __half h = __float2half_rn(W1[idx]);
    int o = n * HD + (k & 255);
    if (k < HD) g_wd[o] = h;
    else        g_wt[o] = h;
}

// ---------------------------------------------------------------------------
// HMMA GEMM (mma.sync m16n8k16, fp16 in / fp32 accum):
//   U[M,256](fp16) = A[M,256](fp32) @ W[256,256]
// Fused over both tables: blockIdx.x < NBLK_D -> drug, else target.
// 128x128 CTA tile, BK=32, 8 warps (warp tile 32x64), double-buffered SMEM.
// ---------------------------------------------------------------------------
#define BK 32
#define APAD 40   // padded k-stride in halves

__global__ __launch_bounds__(256, 1)
void gemm_hmma_kernel(const float* __restrict__ zd, const float* __restrict__ zt) {
    __shared__ __align__(16) __half As[2][128][APAD];
    __shared__ __align__(16) __half Bs[2][128][APAD];

    const int blk = blockIdx.x;
    const float* A; const __half* B; __half* U; int M, bm;
    if (blk < NBLK_D) { A = zd; B = g_wd; U = g_ud; M = N_DRUG; bm = blk * 128; }
    else              { A = zt; B = g_wt; U = g_ut; M = N_TGT;  bm = (blk - NBLK_D) * 128; }
    const int bn   = blockIdx.y * 128;
    const int tid  = threadIdx.x;
    const int lane = tid & 31;
    const int wid  = tid >> 5;
    const int wm   = (wid & 3) * 32;   // warp m offset
    const int wn   = (wid >> 2) * 64;  // warp n offset

    // global load mapping: 2 threads per row, each 16 elements of the 32-wide chunk
    const int arow = tid >> 1, aseg = tid & 1;
    const int ag   = min(bm + arow, M - 1);
    const float4* Ag = reinterpret_cast<const float4*>(A + (size_t)ag * HD) + aseg * 4;
    const uint4*  Bg = reinterpret_cast<const uint4*>(B + (size_t)(bn + arow) * HD) + aseg * 2;

    float acc[2][8][4];
    #pragma unroll
    for (int i = 0; i < 2; ++i)
        #pragma unroll
        for (int j = 0; j < 8; ++j)
            #pragma unroll
            for (int q = 0; q < 4; ++q) acc[i][j][q] = 0.f;

    float4 va[4]; uint4 vb[2];

    auto store_tiles = [&](int buf) {
        uint32_t h[8];
        #pragma unroll
        for (int i = 0; i < 4; ++i) {
            __half2 p0 = __float22half2_rn(make_float2(va[i].x, va[i].y));
            __half2 p1 = __float22half2_rn(make_float2(va[i].z, va[i].w));
            h[2 * i]     = *reinterpret_cast<uint32_t*>(&p0);
            h[2 * i + 1] = *reinterpret_cast<uint32_t*>(&p1);
        }
        uint4* ap = reinterpret_cast<uint4*>(&As[buf][arow][aseg * 16]);
        ap[0] = make_uint4(h[0], h[1], h[2], h[3]);
        ap[1] = make_uint4(h[4], h[5], h[6], h[7]);
        uint4* bp = reinterpret_cast<uint4*>(&Bs[buf][arow][aseg * 16]);
        bp[0] = vb[0];
        bp[1] = vb[1];
    };

    // preload chunk 0
    #pragma unroll
    for (int i = 0; i < 4; ++i) va[i] = Ag[i];
    vb[0] = Bg[0]; vb[1] = Bg[1];
    store_tiles(0);
    __syncthreads();

    #pragma unroll 1
    for (int ck = 0; ck < 8; ++ck) {
        const int buf = ck & 1;
        if (ck < 7) {
            #pragma unroll
            for (int i = 0; i < 4; ++i) va[i] = Ag[(ck + 1) * 8 + i];
            vb[0] = Bg[(ck + 1) * 4];
            vb[1] = Bg[(ck + 1) * 4 + 1];
        }

        #pragma unroll
        for (int ks = 0; ks < 2; ++ks) {
            uint32_t af[2][4], bf[4][4];
            #pragma unroll
            for (int mt = 0; mt < 2; ++mt) {
                uint32_t addr = smem_u32(&As[buf][wm + mt * 16 + (lane & 15)]
                                            [ks * 16 + (lane >> 4) * 8]);
                asm volatile("ldmatrix.sync.aligned.m8n8.x4.shared.b16 {%0,%1,%2,%3}, [%4];"
                             : "=r"(af[mt][0]), "=r"(af[mt][1]), "=r"(af[mt][2]), "=r"(af[mt][3])
                             : "r"(addr));
            }
            #pragma unroll
            for (int q = 0; q < 4; ++q) {
                uint32_t addr = smem_u32(&Bs[buf][wn + q * 16 + (lane & 15)]
                                            [ks * 16 + (lane >> 4) * 8]);
                asm volatile("ldmatrix.sync.aligned.m8n8.x4.shared.b16 {%0,%1,%2,%3}, [%4];"
                             : "=r"(bf[q][0]), "=r"(bf[q][1]), "=r"(bf[q][2]), "=r"(bf[q][3])
                             : "r"(addr));
            }
            #pragma unroll
            for (int mt = 0; mt < 2; ++mt)
                #pragma unroll
                for (int nt = 0; nt < 8; ++nt) {
                    const int q = nt >> 1, s = nt & 1;
                    asm volatile(
                        "mma.sync.aligned.m16n8k16.row.col.f32.f16.f16.f32 "
                        "{%0,%1,%2,%3}, {%4,%5,%6,%7}, {%8,%9}, {%0,%1,%2,%3};"
                        : "+f"(acc[mt][nt][0]), "+f"(acc[mt][nt][1]),
                          "+f"(acc[mt][nt][2]), "+f"(acc[mt][nt][3])
                        : "r"(af[mt][0]), "r"(af[mt][1]), "r"(af[mt][2]), "r"(af[mt][3]),
                          "r"(bf[q][s]), "r"(bf[q][s + 2]));
                }
        }

        if (ck < 7) {
            store_tiles(buf ^ 1);
            __syncthreads();
        }
    }

    // epilogue: fp32 acc -> fp16 U, direct stores
    #pragma unroll
    for (int mt = 0; mt < 2; ++mt) {
        #pragma unroll
        for (int hr = 0; hr < 2; ++hr) {
            int r = bm + wm + mt * 16 + hr * 8 + (lane >> 2);
            if (r < M) {
                __half* up = U + (size_t)r * HD + bn + wn + (lane & 3) * 2;
                #pragma unroll
                for (int nt = 0; nt < 8; ++nt) {
                    __half2 v = __float22half2_rn(
                        make_float2(acc[mt][nt][hr * 2], acc[mt][nt][hr * 2 + 1]));
                    *reinterpret_cast<__half2*>(up + nt * 8) = v;
                }
            }
        }
    }
}

// ---------------------------------------------------------------------------
// Edge kernel: out[e] = relu(u_d[row[e]] + u_t[col[e]] + b1) . W2 + b2
// One warp per edge; each lane reads 16B of each fp16 row (512B coalesced).
// ---------------------------------------------------------------------------
__global__ __launch_bounds__(256)
void edge_kernel(const void* __restrict__ rowp, const void* __restrict__ colp,
                 const float* __restrict__ b1, const float* __restrict__ W2,
                 const float* __restrict__ b2, float* __restrict__ out, int E) {
    __shared__ float s_b1[HD];
    __shared__ float s_w2[HD];
    const int tid = threadIdx.x;
    s_b1[tid] = b1[tid];
    s_w2[tid] = W2[tid];
    __syncthreads();

    const int warp = tid >> 5;
    const int lane = tid & 31;
    const int e = blockIdx.x * 8 + warp;
    if (e >= E) return;

    long long r, c;
    if (g_idx64) {
        r = reinterpret_cast<const long long*>(rowp)[e];
        c = reinterpret_cast<const long long*>(colp)[e];
    } else {
        r = reinterpret_cast<const int*>(rowp)[e];
        c = reinterpret_cast<const int*>(colp)[e];
    }

    uint4 a = reinterpret_cast<const uint4*>(g_ud + (size_t)r * HD)[lane];
    uint4 b = reinterpret_cast<const uint4*>(g_ut + (size_t)c * HD)[lane];
    const __half2* ah = reinterpret_cast<const __half2*>(&a);
    const __half2* bh = reinterpret_cast<const __half2*>(&b);

    float4 bb0 = *reinterpret_cast<const float4*>(&s_b1[lane * 8]);
    float4 bb1 = *reinterpret_cast<const float4*>(&s_b1[lane * 8 + 4]);
    float4 ww0 = *reinterpret_cast<const float4*>(&s_w2[lane * 8]);
    float4 ww1 = *reinterpret_cast<const float4*>(&s_w2[lane * 8 + 4]);
    float bbr[8] = {bb0.x, bb0.y, bb0.z, bb0.w, bb1.x, bb1.y, bb1.z, bb1.w};
    float wwr[8] = {ww0.x, ww0.y, ww0.z, ww0.w, ww1.x, ww1.y, ww1.z, ww1.w};

    float sum = 0.f;
    #pragma unroll
    for (int j = 0; j < 4; ++j) {
        float2 fa = __half22float2(ah[j]);
        float2 fb = __half22float2(bh[j]);
        float h0 = fmaxf(fa.x + fb.x + bbr[2 * j],     0.f);
        float h1 = fmaxf(fa.y + fb.y + bbr[2 * j + 1], 0.f);
        sum = fmaf(h0, wwr[2 * j],     sum);
        sum = fmaf(h1, wwr[2 * j + 1], sum);
    }

    #pragma unroll
    for (int off = 16; off > 0; off >>= 1)
        sum += __shfl_down_sync(0xffffffffu, sum, off);

    if (lane == 0) out[e] = sum + b2[0];
}

// ---------------------------------------------------------------------------
// inputs: 0=z_drug 1=z_target 2=row 3=col 4=W1[512,256] 5=b1 6=W2 7=b2
// ---------------------------------------------------------------------------
extern "C" void kernel_launch(void* const* d_in, const int* in_sizes, int n_in,
                              void* d_out, int out_size) {
    const float* z_drug   = (const float*)d_in[0];
    const float* z_target = (const float*)d_in[1];
    const void*  rowp     = d_in[2];
    const void*  colp     = d_in[3];
    const float* W1       = (const float*)d_in[4];
    const float* b1       = (const float*)d_in[5];
    const float* W2       = (const float*)d_in[6];
    const float* b2       = (const float*)d_in[7];
    float* out = (float*)d_out;
    const int E = out_size;

    detect_idx_kernel<<<1, 32>>>((const unsigned long long*)rowp);
    prep_w1_kernel<<<512, 256>>>(W1);

    dim3 grid(NBLK_D + NBLK_T, 2);
    gemm_hmma_kernel<<<grid, 256>>>(z_drug, z_target);

    edge_kernel<<<(E + 7) / 8, 256>>>(rowp, colp, b1, W2, b2, out, E);
}

// round 4
// speedup vs baseline: 1.8394x; 1.0011x over previous
#include <cuda_runtime.h>
#include <cuda_fp16.h>
#include <stdint.h>

#define HD      256
#define N_DRUG  50000
#define N_TGT   20000
#define NBLK_D  391   // ceil(50000/128)
#define NBLK_T  157   // ceil(20000/128)

// ---------------- device scratch (no allocation allowed) -------------------
__device__ __align__(16) __half g_ud[(size_t)N_DRUG * HD];   // 25.6 MB fp16
__device__ __align__(16) __half g_ut[(size_t)N_TGT  * HD];   // 10.2 MB fp16
// W1 transposed to [n][k] fp16 (K-contiguous rows => "col-major B" for mma.sync)
__device__ __align__(16) __half g_wd[HD * HD];
__device__ __align__(16) __half g_wt[HD * HD];
__device__ int g_idx64;

__device__ __forceinline__ uint32_t smem_u32(const void* p) {
    uint32_t a;
    asm("{ .reg .u64 t; cvta.to.shared.u64 t, %1; cvt.u32.u64 %0, t; }" : "=r"(a) : "l"(p));
    return a;
}

// ---------------------------------------------------------------------------
// index width detection (int64 vs int32 ambiguity of the reference dtypes)
// ---------------------------------------------------------------------------
__global__ void detect_idx_kernel(const unsigned long long* __restrict__ row) {
    if (threadIdx.x == 0 && blockIdx.x == 0) {
        int ok = 1;
        #pragma unroll 1
        for (int i = 0; i < 64; ++i)
            if (row[i] >= (unsigned long long)N_DRUG) { ok = 0; break; }
        g_idx64 = ok;
    }
}

// ---------------------------------------------------------------------------
// W1 prep: transpose [k][n] -> [n][k], fp32 -> fp16
// ---------------------------------------------------------------------------
__global__ void prep_w1_kernel(const float* __restrict__ W1) {
    int idx = blockIdx.x * 256 + threadIdx.x;   // 0 .. 512*256-1
    int k = idx >> 8;
    int n = idx & 255;
    __half h = __float2half_rn(W1[idx]);
    int o = n * HD + (k & 255);
    if (k < HD) g_wd[o] = h;
    else        g_wt[o] = h;
}

// ---------------------------------------------------------------------------
// HMMA GEMM (mma.sync m16n8k16, fp16 in / fp32 accum):
//   U[M,256](fp16) = A[M,256](fp32) @ W[256,256]
// Fused over both tables: blockIdx.x < NBLK_D -> drug, else target.
// 128x128 CTA tile, BK=32, 8 warps (warp tile 32x64), double-buffered SMEM.
// ---------------------------------------------------------------------------
#define BK 32
#define APAD 40   // padded k-stride in halves

__global__ __launch_bounds__(256, 1)
void gemm_hmma_kernel(const float* __restrict__ zd, const float* __restrict__ zt) {
    __shared__ __align__(16) __half As[2][128][APAD];
    __shared__ __align__(16) __half Bs[2][128][APAD];

    const int blk = blockIdx.x;
    const float* A; const __half* B; __half* U; int M, bm;
    if (blk < NBLK_D) { A = zd; B = g_wd; U = g_ud; M = N_DRUG; bm = blk * 128; }
    else              { A = zt; B = g_wt; U = g_ut; M = N_TGT;  bm = (blk - NBLK_D) * 128; }
    const int bn   = blockIdx.y * 128;
    const int tid  = threadIdx.x;
    const int lane = tid & 31;
    const int wid  = tid >> 5;
    const int wm   = (wid & 3) * 32;   // warp m offset
    const int wn   = (wid >> 2) * 64;  // warp n offset

    // global load mapping: 2 threads per row, each 16 elements of the 32-wide chunk
    const int arow = tid >> 1, aseg = tid & 1;
    const int ag   = min(bm + arow, M - 1);
    const float4* Ag = reinterpret_cast<const float4*>(A + (size_t)ag * HD) + aseg * 4;
    const uint4*  Bg = reinterpret_cast<const uint4*>(B + (size_t)(bn + arow) * HD) + aseg * 2;

    float acc[2][8][4];
    #pragma unroll
    for (int i = 0; i < 2; ++i)
        #pragma unroll
        for (int j = 0; j < 8; ++j)
            #pragma unroll
            for (int q = 0; q < 4; ++q) acc[i][j][q] = 0.f;

    float4 va[4]; uint4 vb[2];

    auto store_tiles = [&](int buf) {
        uint32_t h[8];
        #pragma unroll
        for (int i = 0; i < 4; ++i) {
            __half2 p0 = __float22half2_rn(make_float2(va[i].x, va[i].y));
            __half2 p1 = __float22half2_rn(make_float2(va[i].z, va[i].w));
            h[2 * i]     = *reinterpret_cast<uint32_t*>(&p0);
            h[2 * i + 1] = *reinterpret_cast<uint32_t*>(&p1);
        }
        uint4* ap = reinterpret_cast<uint4*>(&As[buf][arow][aseg * 16]);
        ap[0] = make_uint4(h[0], h[1], h[2], h[3]);
        ap[1] = make_uint4(h[4], h[5], h[6], h[7]);
        uint4* bp = reinterpret_cast<uint4*>(&Bs[buf][arow][aseg * 16]);
        bp[0] = vb[0];
        bp[1] = vb[1];
    };

    // preload chunk 0
    #pragma unroll
    for (int i = 0; i < 4; ++i) va[i] = Ag[i];
    vb[0] = Bg[0]; vb[1] = Bg[1];
    store_tiles(0);
    __syncthreads();

    #pragma unroll 1
    for (int ck = 0; ck < 8; ++ck) {
        const int buf = ck & 1;
        if (ck < 7) {
            #pragma unroll
            for (int i = 0; i < 4; ++i) va[i] = Ag[(ck + 1) * 8 + i];
            vb[0] = Bg[(ck + 1) * 4];
            vb[1] = Bg[(ck + 1) * 4 + 1];
        }

        #pragma unroll
        for (int ks = 0; ks < 2; ++ks) {
            uint32_t af[2][4], bf[4][4];
            #pragma unroll
            for (int mt = 0; mt < 2; ++mt) {
                uint32_t addr = smem_u32(&As[buf][wm + mt * 16 + (lane & 15)]
                                            [ks * 16 + (lane >> 4) * 8]);
                asm volatile("ldmatrix.sync.aligned.m8n8.x4.shared.b16 {%0,%1,%2,%3}, [%4];"
                             : "=r"(af[mt][0]), "=r"(af[mt][1]), "=r"(af[mt][2]), "=r"(af[mt][3])
                             : "r"(addr));
            }
            #pragma unroll
            for (int q = 0; q < 4; ++q) {
                uint32_t addr = smem_u32(&Bs[buf][wn + q * 16 + (lane & 15)]
                                            [ks * 16 + (lane >> 4) * 8]);
                asm volatile("ldmatrix.sync.aligned.m8n8.x4.shared.b16 {%0,%1,%2,%3}, [%4];"
                             : "=r"(bf[q][0]), "=r"(bf[q][1]), "=r"(bf[q][2]), "=r"(bf[q][3])
                             : "r"(addr));
            }
            #pragma unroll
            for (int mt = 0; mt < 2; ++mt)
                #pragma unroll
                for (int nt = 0; nt < 8; ++nt) {
                    const int q = nt >> 1, s = nt & 1;
                    asm volatile(
                        "mma.sync.aligned.m16n8k16.row.col.f32.f16.f16.f32 "
                        "{%0,%1,%2,%3}, {%4,%5,%6,%7}, {%8,%9}, {%0,%1,%2,%3};"
                        : "+f"(acc[mt][nt][0]), "+f"(acc[mt][nt][1]),
                          "+f"(acc[mt][nt][2]), "+f"(acc[mt][nt][3])
                        : "r"(af[mt][0]), "r"(af[mt][1]), "r"(af[mt][2]), "r"(af[mt][3]),
                          "r"(bf[q][s]), "r"(bf[q][s + 2]));
                }
        }

        if (ck < 7) {
            store_tiles(buf ^ 1);
            __syncthreads();
        }
    }

    // epilogue: fp32 acc -> fp16 U, direct stores
    #pragma unroll
    for (int mt = 0; mt < 2; ++mt) {
        #pragma unroll
        for (int hr = 0; hr < 2; ++hr) {
            int r = bm + wm + mt * 16 + hr * 8 + (lane >> 2);
            if (r < M) {
                __half* up = U + (size_t)r * HD + bn + wn + (lane & 3) * 2;
                #pragma unroll
                for (int nt = 0; nt < 8; ++nt) {
                    __half2 v = __float22half2_rn(
                        make_float2(acc[mt][nt][hr * 2], acc[mt][nt][hr * 2 + 1]));
                    *reinterpret_cast<__half2*>(up + nt * 8) = v;
                }
            }
        }
    }
}

// ---------------------------------------------------------------------------
// Edge kernel: out[e] = relu(u_d[row[e]] + u_t[col[e]] + b1) . W2 + b2
// One warp per edge; each lane reads 16B of each fp16 row (512B coalesced).
// ---------------------------------------------------------------------------
__global__ __launch_bounds__(256)
void edge_kernel(const void* __restrict__ rowp, const void* __restrict__ colp,
                 const float* __restrict__ b1, const float* __restrict__ W2,
                 const float* __restrict__ b2, float* __restrict__ out, int E) {
    __shared__ float s_b1[HD];
    __shared__ float s_w2[HD];
    const int tid = threadIdx.x;
    s_b1[tid] = b1[tid];
    s_w2[tid] = W2[tid];
    __syncthreads();

    const int warp = tid >> 5;
    const int lane = tid & 31;
    const int e = blockIdx.x * 8 + warp;
    if (e >= E) return;

    long long r, c;
    if (g_idx64) {
        r = reinterpret_cast<const long long*>(rowp)[e];
        c = reinterpret_cast<const long long*>(colp)[e];
    } else {
        r = reinterpret_cast<const int*>(rowp)[e];
        c = reinterpret_cast<const int*>(colp)[e];
    }

    uint4 a = reinterpret_cast<const uint4*>(g_ud + (size_t)r * HD)[lane];
    uint4 b = reinterpret_cast<const uint4*>(g_ut + (size_t)c * HD)[lane];
    const __half2* ah = reinterpret_cast<const __half2*>(&a);
    const __half2* bh = reinterpret_cast<const __half2*>(&b);

    float4 bb0 = *reinterpret_cast<const float4*>(&s_b1[lane * 8]);
    float4 bb1 = *reinterpret_cast<const float4*>(&s_b1[lane * 8 + 4]);
    float4 ww0 = *reinterpret_cast<const float4*>(&s_w2[lane * 8]);
    float4 ww1 = *reinterpret_cast<const float4*>(&s_w2[lane * 8 + 4]);
    float bbr[8] = {bb0.x, bb0.y, bb0.z, bb0.w, bb1.x, bb1.y, bb1.z, bb1.w};
    float wwr[8] = {ww0.x, ww0.y, ww0.z, ww0.w, ww1.x, ww1.y, ww1.z, ww1.w};

    float sum = 0.f;
    #pragma unroll
    for (int j = 0; j < 4; ++j) {
        float2 fa = __half22float2(ah[j]);
        float2 fb = __half22float2(bh[j]);
        float h0 = fmaxf(fa.x + fb.x + bbr[2 * j],     0.f);
        float h1 = fmaxf(fa.y + fb.y + bbr[2 * j + 1], 0.f);
        sum = fmaf(h0, wwr[2 * j],     sum);
        sum = fmaf(h1, wwr[2 * j + 1], sum);
    }

    #pragma unroll
    for (int off = 16; off > 0; off >>= 1)
        sum += __shfl_down_sync(0xffffffffu, sum, off);

    if (lane == 0) out[e] = sum + b2[0];
}

// ---------------------------------------------------------------------------
// inputs: 0=z_drug 1=z_target 2=row 3=col 4=W1[512,256] 5=b1 6=W2 7=b2
// ---------------------------------------------------------------------------
extern "C" void kernel_launch(void* const* d_in, const int* in_sizes, int n_in,
                              void* d_out, int out_size) {
    const float* z_drug   = (const float*)d_in[0];
    const float* z_target = (const float*)d_in[1];
    const void*  rowp     = d_in[2];
    const void*  colp     = d_in[3];
    const float* W1       = (const float*)d_in[4];
    const float* b1       = (const float*)d_in[5];
    const float* W2       = (const float*)d_in[6];
    const float* b2       = (const float*)d_in[7];
    float* out = (float*)d_out;
    const int E = out_size;

    detect_idx_kernel<<<1, 32>>>((const unsigned long long*)rowp);
    prep_w1_kernel<<<512, 256>>>(W1);

    dim3 grid(NBLK_D + NBLK_T, 2);
    gemm_hmma_kernel<<<grid, 256>>>(z_drug, z_target);

    edge_kernel<<<(E + 7) / 8, 256>>>(rowp, colp, b1, W2, b2, out, E);
}

// round 5
// speedup vs baseline: 2.9275x; 1.5916x over previous
#include <cuda_runtime.h>
#include <cuda_fp16.h>
#include <stdint.h>

#define HD      256
#define N_DRUG  50000
#define N_TGT   20000
#define NBLK_D  391   // ceil(50000/128)
#define NBLK_T  157   // ceil(20000/128)

// ---------------- device scratch (no allocation allowed) -------------------
__device__ __align__(16) __half g_ud[(size_t)N_DRUG * HD];   // 25.6 MB fp16 (holds u_drug + b1)
__device__ __align__(16) __half g_ut[(size_t)N_TGT  * HD];   // 10.2 MB fp16
// W1 transposed to [n][k] fp16 (K-contiguous rows => "col-major B" for mma.sync)
__device__ __align__(16) __half g_wd[HD * HD];
__device__ __align__(16) __half g_wt[HD * HD];
__device__ int g_idx64;

__device__ __forceinline__ uint32_t smem_u32(const void* p) {
    uint32_t a;
    asm("{ .reg .u64 t; cvta.to.shared.u64 t, %1; cvt.u32.u64 %0, t; }" : "=r"(a) : "l"(p));
    return a;
}

// ---------------------------------------------------------------------------
// W1 prep: transpose [k][n] -> [n][k], fp32 -> fp16.  Block 0 also runs the
// int64-vs-int32 index width detection (JAX x64 dtype ambiguity).
// ---------------------------------------------------------------------------
__global__ void prep_w1_kernel(const float* __restrict__ W1,
                               const unsigned long long* __restrict__ row) {
    if (blockIdx.x == 0 && threadIdx.x == 0) {
        int ok = 1;
        #pragma unroll 1
        for (int i = 0; i < 64; ++i)
            if (row[i] >= (unsigned long long)N_DRUG) { ok = 0; break; }
        g_idx64 = ok;
    }
    int idx = blockIdx.x * 256 + threadIdx.x;   // 0 .. 512*256-1
    int k = idx >> 8;
    int n = idx & 255;
    __half h = __float2half_rn(W1[idx]);
    int o = n * HD + (k & 255);
    if (k < HD) g_wd[o] = h;
    else        g_wt[o] = h;
}

// ---------------------------------------------------------------------------
// HMMA GEMM (mma.sync m16n8k16, fp16 in / fp32 accum):
//   U[M,256](fp16) = A[M,256](fp32) @ W[256,256]  (+ b1 folded into drug table)
// Fused over both tables: blockIdx.x < NBLK_D -> drug, else target.
// 128x128 CTA tile, BK=32, 8 warps (warp tile 32x64), double-buffered SMEM.
// ---------------------------------------------------------------------------
#define APAD 40   // padded k-stride in halves

__global__ __launch_bounds__(256, 1)
void gemm_hmma_kernel(const float* __restrict__ zd, const float* __restrict__ zt,
                      const float* __restrict__ b1) {
    __shared__ __align__(16) __half As[2][128][APAD];
    __shared__ __align__(16) __half Bs[2][128][APAD];

    const int blk = blockIdx.x;
    const float* A; const __half* B; __half* U; int M, bm; const float* bias;
    if (blk < NBLK_D) { A = zd; B = g_wd; U = g_ud; M = N_DRUG; bm = blk * 128; bias = b1; }
    else  { A = zt; B = g_wt; U = g_ut; M = N_TGT; bm = (blk - NBLK_D) * 128; bias = nullptr; }
    const int bn   = blockIdx.y * 128;
    const int tid  = threadIdx.x;
    const int lane = tid & 31;
    const int wid  = tid >> 5;
    const int wm   = (wid & 3) * 32;   // warp m offset
    const int wn   = (wid >> 2) * 64;  // warp n offset

    // global load mapping: 2 threads per row, each 16 elements of the 32-wide chunk
    const int arow = tid >> 1, aseg = tid & 1;
    const int ag   = min(bm + arow, M - 1);
    const float4* Ag = reinterpret_cast<const float4*>(A + (size_t)ag * HD) + aseg * 4;
    const uint4*  Bg = reinterpret_cast<const uint4*>(B + (size_t)(bn + arow) * HD) + aseg * 2;

    float acc[2][8][4];
    #pragma unroll
    for (int i = 0; i < 2; ++i)
        #pragma unroll
        for (int j = 0; j < 8; ++j)
            #pragma unroll
            for (int q = 0; q < 4; ++q) acc[i][j][q] = 0.f;

    float4 va[4]; uint4 vb[2];

    auto store_tiles = [&](int buf) {
        uint32_t h[8];
        #pragma unroll
        for (int i = 0; i < 4; ++i) {
            __half2 p0 = __float22half2_rn(make_float2(va[i].x, va[i].y));
            __half2 p1 = __float22half2_rn(make_float2(va[i].z, va[i].w));
            h[2 * i]     = *reinterpret_cast<uint32_t*>(&p0);
            h[2 * i + 1] = *reinterpret_cast<uint32_t*>(&p1);
        }
        uint4* ap = reinterpret_cast<uint4*>(&As[buf][arow][aseg * 16]);
        ap[0] = make_uint4(h[0], h[1], h[2], h[3]);
        ap[1] = make_uint4(h[4], h[5], h[6], h[7]);
        uint4* bp = reinterpret_cast<uint4*>(&Bs[buf][arow][aseg * 16]);
        bp[0] = vb[0];
        bp[1] = vb[1];
    };

    // preload chunk 0
    #pragma unroll
    for (int i = 0; i < 4; ++i) va[i] = Ag[i];
    vb[0] = Bg[0]; vb[1] = Bg[1];
    store_tiles(0);
    __syncthreads();

    #pragma unroll 1
    for (int ck = 0; ck < 8; ++ck) {
        const int buf = ck & 1;
        if (ck < 7) {
            #pragma unroll
            for (int i = 0; i < 4; ++i) va[i] = Ag[(ck + 1) * 8 + i];
            vb[0] = Bg[(ck + 1) * 4];
            vb[1] = Bg[(ck + 1) * 4 + 1];
        }

        #pragma unroll
        for (int ks = 0; ks < 2; ++ks) {
            uint32_t af[2][4], bf[4][4];
            #pragma unroll
            for (int mt = 0; mt < 2; ++mt) {
                uint32_t addr = smem_u32(&As[buf][wm + mt * 16 + (lane & 15)]
                                            [ks * 16 + (lane >> 4) * 8]);
                asm volatile("ldmatrix.sync.aligned.m8n8.x4.shared.b16 {%0,%1,%2,%3}, [%4];"
                             : "=r"(af[mt][0]), "=r"(af[mt][1]), "=r"(af[mt][2]), "=r"(af[mt][3])
                             : "r"(addr));
            }
            #pragma unroll
            for (int q = 0; q < 4; ++q) {
                uint32_t addr = smem_u32(&Bs[buf][wn + q * 16 + (lane & 15)]
                                            [ks * 16 + (lane >> 4) * 8]);
                asm volatile("ldmatrix.sync.aligned.m8n8.x4.shared.b16 {%0,%1,%2,%3}, [%4];"
                             : "=r"(bf[q][0]), "=r"(bf[q][1]), "=r"(bf[q][2]), "=r"(bf[q][3])
                             : "r"(addr));
            }
            #pragma unroll
            for (int mt = 0; mt < 2; ++mt)
                #pragma unroll
                for (int nt = 0; nt < 8; ++nt) {
                    const int q = nt >> 1, s = nt & 1;
                    asm volatile(
                        "mma.sync.aligned.m16n8k16.row.col.f32.f16.f16.f32 "
                        "{%0,%1,%2,%3}, {%4,%5,%6,%7}, {%8,%9}, {%0,%1,%2,%3};"
                        : "+f"(acc[mt][nt][0]), "+f"(acc[mt][nt][1]),
                          "+f"(acc[mt][nt][2]), "+f"(acc[mt][nt][3])
                        : "r"(af[mt][0]), "r"(af[mt][1]), "r"(af[mt][2]), "r"(af[mt][3]),
                          "r"(bf[q][s]), "r"(bf[q][s + 2]));
                }
        }

        if (ck < 7) {
            store_tiles(buf ^ 1);
            __syncthreads();
        }
    }

    // per-column bias (b1 folded into the drug table)
    float2 bv[8];
    #pragma unroll
    for (int nt = 0; nt < 8; ++nt) bv[nt] = make_float2(0.f, 0.f);
    if (bias) {
        #pragma unroll
        for (int nt = 0; nt < 8; ++nt)
            bv[nt] = *reinterpret_cast<const float2*>(bias + bn + wn + nt * 8 + (lane & 3) * 2);
    }

    // epilogue: fp32 acc (+bias) -> fp16 U, direct stores
    #pragma unroll
    for (int mt = 0; mt < 2; ++mt) {
        #pragma unroll
        for (int hr = 0; hr < 2; ++hr) {
            int r = bm + wm + mt * 16 + hr * 8 + (lane >> 2);
            if (r < M) {
                __half* up = U + (size_t)r * HD + bn + wn + (lane & 3) * 2;
                #pragma unroll
                for (int nt = 0; nt < 8; ++nt) {
                    __half2 v = __float22half2_rn(
                        make_float2(acc[mt][nt][hr * 2] + bv[nt].x,
                                    acc[mt][nt][hr * 2 + 1] + bv[nt].y));
                    *reinterpret_cast<__half2*>(up + nt * 8) = v;
                }
            }
        }
    }
}

// ---------------------------------------------------------------------------
// Edge kernel: out[e] = relu(u_d[row[e]] + u_t[col[e]]) . W2 + b2   (b1 folded)
// 8 lanes per edge (4 edges/warp): lane sub handles 32 hidden dims via 4 uint4
// gathers per table at interleaved offsets (i*8+sub) -> one 128B sector per
// group per load. w2 slice lives in 32 registers, reused across grid-stride.
// ---------------------------------------------------------------------------
__global__ __launch_bounds__(256)
void edge_kernel(const void* __restrict__ rowp, const void* __restrict__ colp,
                 const float* __restrict__ W2, const float* __restrict__ b2,
                 float* __restrict__ out, int E) {
    __shared__ float s_w2[HD];
    const int tid = threadIdx.x;
    s_w2[tid] = W2[tid];
    __syncthreads();

    const int lane = tid & 31;
    const int wid  = tid >> 5;
    const int sub  = lane & 7;   // position within 8-lane group
    const int g    = lane >> 3;  // group (edge) within warp

    // this lane's 32 w2 values: dims {(i*8+sub)*8 + t : i in 0..3, t in 0..7}
    float w2r[32];
    #pragma unroll
    for (int i = 0; i < 4; ++i) {
        float4 v0 = *reinterpret_cast<const float4*>(&s_w2[(i * 8 + sub) * 8]);
        float4 v1 = *reinterpret_cast<const float4*>(&s_w2[(i * 8 + sub) * 8 + 4]);
        w2r[i * 8 + 0] = v0.x; w2r[i * 8 + 1] = v0.y;
        w2r[i * 8 + 2] = v0.z; w2r[i * 8 + 3] = v0.w;
        w2r[i * 8 + 4] = v1.x; w2r[i * 8 + 5] = v1.y;
        w2r[i * 8 + 6] = v1.z; w2r[i * 8 + 7] = v1.w;
    }
    const float bias2 = b2[0];
    const bool idx64 = (g_idx64 != 0);
    const __half2 zero2 = __float2half2_rn(0.f);

    for (int e = blockIdx.x * 32 + wid * 4 + g; e < E; e += gridDim.x * 32) {
        long long r, c;
        if (idx64) {
            r = reinterpret_cast<const long long*>(rowp)[e];
            c = reinterpret_cast<const long long*>(colp)[e];
        } else {
            r = reinterpret_cast<const int*>(rowp)[e];
            c = reinterpret_cast<const int*>(colp)[e];
        }
        const uint4* ap = reinterpret_cast<const uint4*>(g_ud + (size_t)r * HD);
        const uint4* bp = reinterpret_cast<const uint4*>(g_ut + (size_t)c * HD);

        uint4 av[4], bv[4];
        #pragma unroll
        for (int i = 0; i < 4; ++i) av[i] = ap[i * 8 + sub];
        #pragma unroll
        for (int i = 0; i < 4; ++i) bv[i] = bp[i * 8 + sub];

        float sum = 0.f;
        #pragma unroll
        for (int i = 0; i < 4; ++i) {
            const __half2* ah = reinterpret_cast<const __half2*>(&av[i]);
            const __half2* bh = reinterpret_cast<const __half2*>(&bv[i]);
            #pragma unroll
            for (int j = 0; j < 4; ++j) {
                __half2 h = __hmax2(__hadd2(ah[j], bh[j]), zero2);
                float2 f = __half22float2(h);
                sum = fmaf(f.x, w2r[i * 8 + j * 2],     sum);
                sum = fmaf(f.y, w2r[i * 8 + j * 2 + 1], sum);
            }
        }

        sum += __shfl_xor_sync(0xffffffffu, sum, 4);
        sum += __shfl_xor_sync(0xffffffffu, sum, 2);
        sum += __shfl_xor_sync(0xffffffffu, sum, 1);
        if (sub == 0) out[e] = sum + bias2;
    }
}

// ---------------------------------------------------------------------------
// inputs: 0=z_drug 1=z_target 2=row 3=col 4=W1[512,256] 5=b1 6=W2 7=b2
// ---------------------------------------------------------------------------
extern "C" void kernel_launch(void* const* d_in, const int* in_sizes, int n_in,
                              void* d_out, int out_size) {
    const float* z_drug   = (const float*)d_in[0];
    const float* z_target = (const float*)d_in[1];
    const void*  rowp     = d_in[2];
    const void*  colp     = d_in[3];
    const float* W1       = (const float*)d_in[4];
    const float* b1       = (const float*)d_in[5];
    const float* W2       = (const float*)d_in[6];
    const float* b2       = (const float*)d_in[7];
    float* out = (float*)d_out;
    const int E = out_size;

    prep_w1_kernel<<<512, 256>>>(W1, (const unsigned long long*)rowp);

    dim3 grid(NBLK_D + NBLK_T, 2);
    gemm_hmma_kernel<<<grid, 256>>>(z_drug, z_target, b1);

    edge_kernel<<<2048, 256>>>(rowp, colp, W2, b2, out, E);
}

// round 6
// speedup vs baseline: 3.8948x; 1.3304x over previous
#include <cuda_runtime.h>
#include <cuda_fp16.h>
#include <stdint.h>

#define HD      256
#define N_DRUG  50000
#define N_TGT   20000
#define NB64_D  782   // ceil(50000/64)
#define NB64_T  313   // ceil(20000/64)

// ---------------- device scratch (no allocation allowed) -------------------
__device__ __align__(16) __half g_ud[(size_t)N_DRUG * HD];   // fp16, b1 folded in
__device__ __align__(16) __half g_ut[(size_t)N_TGT  * HD];
// W1 transposed to [n][k] fp16 (K-contiguous rows => col-major B for mma.sync)
__device__ __align__(16) __half g_wd[HD * HD];
__device__ __align__(16) __half g_wt[HD * HD];
__device__ int g_idx64;

__device__ __forceinline__ uint32_t smem_u32(const void* p) {
    uint32_t a;
    asm("{ .reg .u64 t; cvta.to.shared.u64 t, %1; cvt.u32.u64 %0, t; }" : "=r"(a) : "l"(p));
    return a;
}
#define CP_ASYNC_16(dst, src) \
    asm volatile("cp.async.cg.shared.global [%0], [%1], 16;" :: "r"(dst), "l"(src))
#define CP_ASYNC_COMMIT() asm volatile("cp.async.commit_group;")
#define CP_ASYNC_WAIT0()  asm volatile("cp.async.wait_group 0;")

// ---------------------------------------------------------------------------
// W1 prep: transpose [k][n] -> [n][k], fp32 -> fp16; block 0 thread 0 also
// detects int64-vs-int32 index width (JAX x64 dtype ambiguity).
// ---------------------------------------------------------------------------
__global__ void prep_w1_kernel(const float* __restrict__ W1,
                               const unsigned long long* __restrict__ row) {
    if (blockIdx.x == 0 && threadIdx.x == 0) {
        int ok = 1;
        #pragma unroll 1
        for (int i = 0; i < 64; ++i)
            if (row[i] >= (unsigned long long)N_DRUG) { ok = 0; break; }
        g_idx64 = ok;
    }
    int idx = blockIdx.x * 256 + threadIdx.x;   // 0 .. 512*256-1
    int k = idx >> 8;
    int n = idx & 255;
    __half h = __float2half_rn(W1[idx]);
    int o = n * HD + (k & 255);
    if (k < HD) g_wd[o] = h;
    else        g_wt[o] = h;
}

// ---------------------------------------------------------------------------
// HMMA GEMM:  U[M,256](fp16) = A[M,256](fp32) @ W[256,256]  (+b1 for drug)
// 64m x 256n CTA tile, BK=32, double-buffered; B via cp.async.cg (fp16),
// A register-staged with fp32->fp16 convert. 8 warps = 2m x 4n (32x64 each).
// ---------------------------------------------------------------------------
#define APAD 40   // padded k-stride in halves (80 B rows, 16B aligned)

__global__ __launch_bounds__(256, 2)
void gemm_hmma_kernel(const float* __restrict__ zd, const float* __restrict__ zt,
                      const float* __restrict__ b1) {
    __shared__ __align__(16) __half As[2][64][APAD];
    __shared__ __align__(16) __half Bs[2][256][APAD];

    const int blk = blockIdx.x;
    const float* A; const __half* B; __half* U; int M, bm; const float* bias;
    if (blk < NB64_D) { A = zd; B = g_wd; U = g_ud; M = N_DRUG; bm = blk * 64; bias = b1; }
    else { A = zt; B = g_wt; U = g_ut; M = N_TGT; bm = (blk - NB64_D) * 64; bias = nullptr; }

    const int tid  = threadIdx.x;
    const int lane = tid & 31;
    const int wid  = tid >> 5;
    const int wm   = (wid & 1) * 32;   // warp m offset (0/32)
    const int wn   = (wid >> 1) * 64;  // warp n offset (0/64/128/192)

    // A load mapping: 4 threads per row, 8 fp32 (2 float4) each
    const int arow = tid >> 2, aseg = tid & 3;
    const int ag   = min(bm + arow, M - 1);
    const float4* Ag = reinterpret_cast<const float4*>(A + (size_t)ag * HD);

    float acc[2][8][4];
    #pragma unroll
    for (int i = 0; i < 2; ++i)
        #pragma unroll
        for (int j = 0; j < 8; ++j)
            #pragma unroll
            for (int q = 0; q < 4; ++q) acc[i][j][q] = 0.f;

    float4 va[2];

    auto issue_b = [&](int buf, int ck) {
        #pragma unroll
        for (int i = 0; i < 4; ++i) {
            int idx = i * 256 + tid;          // 0..1023
            int n = idx >> 2, c = idx & 3;
            uint32_t dst = smem_u32(&Bs[buf][n][c * 8]);
            const __half* src = B + (size_t)n * HD + ck * 32 + c * 8;
            CP_ASYNC_16(dst, src);
        }
        CP_ASYNC_COMMIT();
    };
    auto store_a = [&](int buf) {
        uint32_t h[4];
        #pragma unroll
        for (int i = 0; i < 2; ++i) {
            __half2 p0 = __float22half2_rn(make_float2(va[i].x, va[i].y));
            __half2 p1 = __float22half2_rn(make_float2(va[i].z, va[i].w));
            h[2 * i]     = *reinterpret_cast<uint32_t*>(&p0);
            h[2 * i + 1] = *reinterpret_cast<uint32_t*>(&p1);
        }
        *reinterpret_cast<uint4*>(&As[buf][arow][aseg * 8]) =
            make_uint4(h[0], h[1], h[2], h[3]);
    };

    // prologue: A(0) regs, B(0) cp.async
    va[0] = Ag[aseg * 2];
    va[1] = Ag[aseg * 2 + 1];
    issue_b(0, 0);

    #pragma unroll 1
    for (int ck = 0; ck < 8; ++ck) {
        const int buf = ck & 1;
        store_a(buf);
        if (ck < 7) {
            va[0] = Ag[(ck + 1) * 8 + aseg * 2];
            va[1] = Ag[(ck + 1) * 8 + aseg * 2 + 1];
        }
        CP_ASYNC_WAIT0();
        __syncthreads();
        if (ck < 7) issue_b(buf ^ 1, ck + 1);

        #pragma unroll
        for (int ks = 0; ks < 2; ++ks) {
            uint32_t af[2][4], bf[4][4];
            #pragma unroll
            for (int mt = 0; mt < 2; ++mt) {
                uint32_t addr = smem_u32(&As[buf][wm + mt * 16 + (lane & 15)]
                                            [ks * 16 + (lane >> 4) * 8]);
                asm volatile("ldmatrix.sync.aligned.m8n8.x4.shared.b16 {%0,%1,%2,%3}, [%4];"
                             : "=r"(af[mt][0]), "=r"(af[mt][1]), "=r"(af[mt][2]), "=r"(af[mt][3])
                             : "r"(addr));
            }
            #pragma unroll
            for (int q = 0; q < 4; ++q) {
                uint32_t addr = smem_u32(&Bs[buf][wn + q * 16 + (lane & 15)]
                                            [ks * 16 + (lane >> 4) * 8]);
                asm volatile("ldmatrix.sync.aligned.m8n8.x4.shared.b16 {%0,%1,%2,%3}, [%4];"
                             : "=r"(bf[q][0]), "=r"(bf[q][1]), "=r"(bf[q][2]), "=r"(bf[q][3])
                             : "r"(addr));
            }
            #pragma unroll
            for (int mt = 0; mt < 2; ++mt)
                #pragma unroll
                for (int nt = 0; nt < 8; ++nt) {
                    const int q = nt >> 1, s = nt & 1;
                    asm volatile(
                        "mma.sync.aligned.m16n8k16.row.col.f32.f16.f16.f32 "
                        "{%0,%1,%2,%3}, {%4,%5,%6,%7}, {%8,%9}, {%0,%1,%2,%3};"
                        : "+f"(acc[mt][nt][0]), "+f"(acc[mt][nt][1]),
                          "+f"(acc[mt][nt][2]), "+f"(acc[mt][nt][3])
                        : "r"(af[mt][0]), "r"(af[mt][1]), "r"(af[mt][2]), "r"(af[mt][3]),
                          "r"(bf[q][s]), "r"(bf[q][s + 2]));
                }
        }
        if (ck < 7) __syncthreads();
    }

    // per-column bias (b1 folded into the drug table)
    float2 bv[8];
    #pragma unroll
    for (int nt = 0; nt < 8; ++nt) bv[nt] = make_float2(0.f, 0.f);
    if (bias) {
        #pragma unroll
        for (int nt = 0; nt < 8; ++nt)
            bv[nt] = *reinterpret_cast<const float2*>(bias + wn + nt * 8 + (lane & 3) * 2);
    }

    // epilogue: fp32 acc (+bias) -> fp16 U
    #pragma unroll
    for (int mt = 0; mt < 2; ++mt) {
        #pragma unroll
        for (int hr = 0; hr < 2; ++hr) {
            int r = bm + wm + mt * 16 + hr * 8 + (lane >> 2);
            if (r < M) {
                __half* up = U + (size_t)r * HD + wn + (lane & 3) * 2;
                #pragma unroll
                for (int nt = 0; nt < 8; ++nt) {
                    __half2 v = __float22half2_rn(
                        make_float2(acc[mt][nt][hr * 2] + bv[nt].x,
                                    acc[mt][nt][hr * 2 + 1] + bv[nt].y));
                    *reinterpret_cast<__half2*>(up + nt * 8) = v;
                }
            }
        }
    }
}

// ---------------------------------------------------------------------------
// Edge kernel: out[e] = relu(u_d[row[e]] + u_t[col[e]]) . W2 + b2   (b1 folded)
// 8 lanes per edge (4 edges/warp); MLP=8 per thread, 3-shuffle reduction.
// ---------------------------------------------------------------------------
__global__ __launch_bounds__(256)
void edge_kernel(const void* __restrict__ rowp, const void* __restrict__ colp,
                 const float* __restrict__ W2, const float* __restrict__ b2,
                 float* __restrict__ out, int E) {
    __shared__ float s_w2[HD];
    const int tid = threadIdx.x;
    s_w2[tid] = W2[tid];
    __syncthreads();

    const int lane = tid & 31;
    const int wid  = tid >> 5;
    const int sub  = lane & 7;
    const int g    = lane >> 3;

    float w2r[32];
    #pragma unroll
    for (int i = 0; i < 4; ++i) {
        float4 v0 = *reinterpret_cast<const float4*>(&s_w2[(i * 8 + sub) * 8]);
        float4 v1 = *reinterpret_cast<const float4*>(&s_w2[(i * 8 + sub) * 8 + 4]);
        w2r[i * 8 + 0] = v0.x; w2r[i * 8 + 1] = v0.y;
        w2r[i * 8 + 2] = v0.z; w2r[i * 8 + 3] = v0.w;
        w2r[i * 8 + 4] = v1.x; w2r[i * 8 + 5] = v1.y;
        w2r[i * 8 + 6] = v1.z; w2r[i * 8 + 7] = v1.w;
    }
    const float bias2 = b2[0];
    const bool idx64 = (g_idx64 != 0);
    const __half2 zero2 = __float2half2_rn(0.f);

    for (int e = blockIdx.x * 32 + wid * 4 + g; e < E; e += gridDim.x * 32) {
        long long r, c;
        if (idx64) {
            r = reinterpret_cast<const long long*>(rowp)[e];
            c = reinterpret_cast<const long long*>(colp)[e];
        } else {
            r = reinterpret_cast<const int*>(rowp)[e];
            c = reinterpret_cast<const int*>(colp)[e];
        }
        const uint4* ap = reinterpret_cast<const uint4*>(g_ud + (size_t)r * HD);
        const uint4* bp = reinterpret_cast<const uint4*>(g_ut + (size_t)c * HD);

        uint4 av[4], bv[4];
        #pragma unroll
        for (int i = 0; i < 4; ++i) av[i] = ap[i * 8 + sub];
        #pragma unroll
        for (int i = 0; i < 4; ++i) bv[i] = bp[i * 8 + sub];

        float sum = 0.f;
        #pragma unroll
        for (int i = 0; i < 4; ++i) {
            const __half2* ah = reinterpret_cast<const __half2*>(&av[i]);
            const __half2* bh = reinterpret_cast<const __half2*>(&bv[i]);
            #pragma unroll
            for (int j = 0; j < 4; ++j) {
                __half2 h = __hmax2(__hadd2(ah[j], bh[j]), zero2);
                float2 f = __half22float2(h);
                sum = fmaf(f.x, w2r[i * 8 + j * 2],     sum);
                sum = fmaf(f.y, w2r[i * 8 + j * 2 + 1], sum);
            }
        }

        sum += __shfl_xor_sync(0xffffffffu, sum, 4);
        sum += __shfl_xor_sync(0xffffffffu, sum, 2);
        sum += __shfl_xor_sync(0xffffffffu, sum, 1);
        if (sub == 0) out[e] = sum + bias2;
    }
}

// ---------------------------------------------------------------------------
// inputs: 0=z_drug 1=z_target 2=row 3=col 4=W1[512,256] 5=b1 6=W2 7=b2
// ---------------------------------------------------------------------------
extern "C" void kernel_launch(void* const* d_in, const int* in_sizes, int n_in,
                              void* d_out, int out_size) {
    const float* z_drug   = (const float*)d_in[0];
    const float* z_target = (const float*)d_in[1];
    const void*  rowp     = d_in[2];
    const void*  colp     = d_in[3];
    const float* W1       = (const float*)d_in[4];
    const float* b1       = (const float*)d_in[5];
    const float* W2       = (const float*)d_in[6];
    const float* b2       = (const float*)d_in[7];
    float* out = (float*)d_out;
    const int E = out_size;

    prep_w1_kernel<<<512, 256>>>(W1, (const unsigned long long*)rowp);
    gemm_hmma_kernel<<<NB64_D + NB64_T, 256>>>(z_drug, z_target, b1);
    edge_kernel<<<2048, 256>>>(rowp, colp, W2, b2, out, E);
}